// round 14
// baseline (speedup 1.0000x reference)
#include <cuda_runtime.h>
#include <math.h>

#define NB   16
#define CINC 12
#define TT   16352
#define ATOM 64
#define NAC  128
#define LL   512
#define NOUT (NB*CINC*TT)
#define SL   16   // l positions per stem block

typedef unsigned long long ull;

// ---------------- device scratch (no allocations allowed) ----------------
__device__ float g_mean[NB*CINC];
__device__ float g_std [NB*CINC];
__device__ float g_zraw[NB*NAC*LL];
__device__ float g_R4  [NB*NAC*LL];     // per-scale recon contributions
__device__ float g_R2  [NB*NAC*LL];
__device__ float g_R1  [NB*NAC*LL];
__device__ float g_W1  [NAC*1*64*NAC];  // folded weights S=1: [ni][jj][no]
__device__ float g_W2  [NAC*2*33*NAC];  // folded weights S=2: [ni][ph][jj][no]
__device__ float g_W4  [NAC*4*17*NAC];  // folded weights S=4: [ni][ph][jj][no]
__device__ float g_w1t [CINC*64*64];    // stem w1 transposed: [c][k][m]
__device__ float g_Wf  [NAC*3*CINC*32]; // folded decoder weights
__device__ float g_part[3*512];         // l1 partials (unused slots stay 0)

// ---------------- packed f32x2 helpers ----------------
__device__ __forceinline__ void ffma2(ull &d, ull a, ull b) {
    asm("fma.rn.f32x2 %0, %1, %2, %0;" : "+l"(d) : "l"(a), "l"(b));
}
__device__ __forceinline__ ull pack2(float lo, float hi) {
    ull r;
    asm("mov.b64 %0, {%1, %2};" : "=l"(r) : "f"(lo), "f"(hi));
    return r;
}
__device__ __forceinline__ float2 unpack2(ull v) {
    float2 r;
    asm("mov.b64 {%0, %1}, %2;" : "=f"(r.x), "=f"(r.y) : "l"(v));
    return r;
}

// ---------------- merged prep: meanstd | shapelet fold | w1 transpose | dec fold ----
// grid 1088: [0,192) meanstd, [192,320) shapelet prep, [320,512) wstem, [512,1088) fold
__global__ void k_prep_all(const float* __restrict__ x,
                           const float* __restrict__ shapelets,
                           const float* __restrict__ w1,
                           const float* __restrict__ dec_w) {
    __shared__ float raw[NAC][ATOM + 1];
    __shared__ float inv[NAC];
    int bx = blockIdx.x;
    int tid = threadIdx.x;

    if (bx < 192) {
        // -------- mean / std per (b,c) --------
        int row = bx;
        const float* xr = x + (size_t)row * TT;
        float s = 0.f, s2 = 0.f;
        for (int t = tid; t < TT; t += 256) {
            float v = xr[t]; s += v; s2 += v*v;
        }
        float* ss = &raw[0][0];
        float* sq = ss + 256;
        ss[tid] = s; sq[tid] = s2;
        __syncthreads();
        for (int o = 128; o > 0; o >>= 1) {
            if (tid < o) { ss[tid] += ss[tid+o]; sq[tid] += sq[tid+o]; }
            __syncthreads();
        }
        if (tid == 0) {
            float m  = ss[0] / (float)TT;
            float var = sq[0] / (float)TT - m*m;
            g_mean[row] = m;
            g_std[row]  = sqrtf(var + 1e-5f);
        }
    } else if (bx < 320) {
        // -------- normalize shapelets + folded transposed weights --------
        int ni = bx - 192;
        for (int i = tid; i < NAC*ATOM; i += 256) {
            int no = i >> 6, k = i & 63;
            raw[no][k] = shapelets[((size_t)no*NAC + ni)*ATOM + k];
        }
        __syncthreads();
        if (tid < NAC) {
            float ssum = 0.f;
            #pragma unroll 8
            for (int k = 0; k < ATOM; k++) { float v = raw[tid][k]; ssum += v*v; }
            inv[tid] = 1.f / fmaxf(sqrtf(ssum), 1e-8f);
        }
        __syncthreads();

        for (int i = tid; i < 64*NAC; i += 256) {
            int no = i & 127, jj = i >> 7;
            g_W1[((size_t)ni*64 + jj)*NAC + no] = raw[no][jj] * inv[no];
        }
        for (int i = tid; i < 2*33*NAC; i += 256) {
            int no = i & 127;
            int rest = i >> 7;
            int jj = rest % 33, ph = rest / 33;
            int k0 = 2*jj - ph, k1 = k0 + 1;
            if (k0 < 0)  k0 = 0;
            if (k1 > 63) k1 = 63;
            float acc = 0.f;
            for (int k = k0; k <= k1; k++) acc += raw[no][k];
            g_W2[((size_t)(ni*2 + ph)*33 + jj)*NAC + no] = acc * inv[no];
        }
        for (int i = tid; i < 4*17*NAC; i += 256) {
            int no = i & 127;
            int rest = i >> 7;
            int jj = rest % 17, ph = rest / 17;
            int k0 = 4*jj - ph, k1 = k0 + 3;
            if (k0 < 0)  k0 = 0;
            if (k1 > 63) k1 = 63;
            float acc = 0.f;
            for (int k = k0; k <= k1; k++) acc += raw[no][k];
            g_W4[((size_t)(ni*4 + ph)*17 + jj)*NAC + no] = acc * inv[no];
        }
    } else if (bx < 512) {
        // -------- stem w1 transpose: g_w1t[(c*64+k)*64+m] = w1[m][c][k] --------
        int id = (bx - 320)*256 + tid;
        if (id < CINC*64*64) {
            int m = id & 63;
            int k = (id >> 6) & 63;
            int c = id >> 12;
            g_w1t[id] = w1[((size_t)m*CINC + c)*ATOM + k];
        }
    } else {
        // -------- fold decoder weights: Wf[na][d][c][r] --------
        int id = (bx - 512)*256 + tid;
        if (id < NAC*3*CINC*32) {
            int r  = id & 31;
            int c  = (id >> 5) % CINC;
            int dd = (id / (32*CINC)) % 3;
            int na = id / (32*CINC*3);
            int k0, k1;
            if (dd == 0)      { k0 = 0;      k1 = 30 - r; }
            else if (dd == 1) { k0 = 31 - r; k1 = 62 - r; }
            else              { k0 = 63 - r; k1 = 63;     }
            float acc = 0.f;
            const float* w = dec_w + ((size_t)c*NAC + na)*ATOM;
            for (int k = k0; k <= k1; k++) acc += w[k];
            g_Wf[((na*3 + dd)*CINC + c)*32 + r] = acc;
        }
    }
}

// ---------------- fused stem (FMA-bound layout + w prefetch) ----------------
__global__ void k_stem(const float* __restrict__ x,
                       const float* __restrict__ b1,
                       const float* __restrict__ w2, const float* __restrict__ b2,
                       const float* __restrict__ scale) {
    extern __shared__ float sm[];
    float* xsdf = sm;                     // 12 * 594 float2 = 14256 floats
    float* w1t  = sm + CINC*594*2;        // 64*68 = 4352 floats
    float* hp   = w1t + 64*68;            // 4*64*16 = 4096 floats
    float* hs   = hp + 4*64*SL;           // 64*16 = 1024 floats
    __shared__ float mn[CINC], isd[CINC];

    int b  = blockIdx.y;
    int l0 = blockIdx.x * SL;
    int tid = threadIdx.x;
    int kq = tid >> 6;
    int lp = (tid >> 3) & 7;
    int mo = tid & 7;

    if (tid < CINC) { mn[tid] = g_mean[b*CINC+tid]; isd[tid] = 1.f / g_std[b*CINC+tid]; }
    __syncthreads();

    int t0 = 32*l0 - 32;
    for (int i = tid; i < CINC*544; i += 256) {
        int c = i / 544, u = i - c*544;
        int t = t0 + u;
        float v = 0.f;
        if (t >= 0 && t < TT) v = (x[((size_t)b*CINC + c)*TT + t] - mn[c]) * isd[c];
        int us = u + (u >> 5);
        float2* dst = (float2*)(xsdf + (c*594 + us)*2);
        *dst = make_float2(v, v);
    }

    float4 pf[4];
    #pragma unroll
    for (int u = 0; u < 4; u++) pf[u] = ((const float4*)g_w1t)[tid + u*256];

    ull acc[4][2];
    #pragma unroll
    for (int p = 0; p < 4; p++) { acc[p][0] = pack2(0.f, 0.f); acc[p][1] = pack2(0.f, 0.f); }

    for (int c = 0; c < CINC; c++) {
        __syncthreads();
        #pragma unroll
        for (int u = 0; u < 4; u++) {
            int i = tid + u*256;
            int k = i >> 4, m4 = (i & 15) * 4;
            *(float4*)(w1t + k*68 + m4) = pf[u];
        }
        __syncthreads();
        if (c + 1 < CINC) {
            const float4* src = (const float4*)(g_w1t + (c+1)*4096);
            #pragma unroll
            for (int u = 0; u < 4; u++) pf[u] = src[tid + u*256];
        }
        const ull* xc2 = (const ull*)(xsdf + c*594*2);
        #pragma unroll 4
        for (int kk = 0; kk < 16; kk++) {
            int k  = 16*kq + kk;
            int u0 = 64*lp + k;
            int u1 = u0 + 32;
            ull x0 = xc2[u0 + (u0 >> 5)];
            ull x1 = xc2[u1 + (u1 >> 5)];
            const ull* wr = (const ull*)(w1t + k*68);
            #pragma unroll
            for (int p = 0; p < 4; p++) {
                ull wv = wr[mo + 8*p];
                ffma2(acc[p][0], wv, x0);
                ffma2(acc[p][1], wv, x1);
            }
        }
    }

    #pragma unroll
    for (int p = 0; p < 4; p++) {
        int m = 2*mo + 16*p;
        #pragma unroll
        for (int j = 0; j < 2; j++) {
            float2 v = unpack2(acc[p][j]);
            int l = 2*lp + j;
            hp[(kq*64 + m)*SL + l]       = v.x;
            hp[(kq*64 + m + 1)*SL + l]   = v.y;
        }
    }
    __syncthreads();
    for (int i = tid; i < 64*SL; i += 256) {
        int m = i >> 4, l = i & 15;
        float s = hp[(0*64+m)*SL + l] + hp[(1*64+m)*SL + l]
                + hp[(2*64+m)*SL + l] + hp[(3*64+m)*SL + l];
        hs[m*SL + l] = fmaxf(s + b1[m], 0.f);
    }
    __syncthreads();

    float sc = scale[0];
    #pragma unroll
    for (int j = 0; j < 8; j++) {
        int idx = tid + j*256;
        int a = idx >> 4, l = idx & 15;
        float z = 0.f;
        const float* w2r = w2 + (size_t)a*64;
        #pragma unroll 8
        for (int m = 0; m < 64; m++) z += hs[m*SL + l] * w2r[m];
        z = (z + b2[a]) * sc;
        g_zraw[((size_t)b*NAC + a)*LL + l0 + l] = z;
    }
}

// ---------------- folded shapelet conv with fused pooling + l1 ----------------
// grid (8, NB): blockIdx.x = wtile*S + r; 64-wide w tiles; 8no x 4w FFMA2 tile.
// IDX: 0 -> scale 4 (no residual sub), 1 -> scale 2 (sub R4), 2 -> scale 1 (sub R4+R2).
// Pools zraw - subs on the fly into Zs; writes own recon buffer; r==0 blocks own l1.
template<int S, int TP, int IDX>
__global__ void __launch_bounds__(256, 1) k_fconv() {
    constexpr int ZW = TP + 64;
    constexpr int ZR = TP + 65;
    constexpr int LS = LL / S;
    constexpr int N4  = TP*NAC/4;
    constexpr int NPF = (N4 + 255) / 256;
    constexpr int ABUF = TP*NAC;
    const float* W    = (S == 4) ? g_W4 : ((S == 2) ? g_W2 : g_W1);
    float* Rout       = (IDX == 0) ? g_R4 : ((IDX == 1) ? g_R2 : g_R1);

    extern __shared__ float smem[];
    float* Zs = smem;                // [NAC][ZR]
    float* As = smem + NAC*ZR;       // 2 x [TP][NAC] double buffer
    __shared__ float red[256];

    int b  = blockIdx.y;
    int wt = blockIdx.x / S;
    int r  = blockIdx.x % S;
    int w0 = wt * 64;
    int q_r = -(((31 - r) + S - 1) / S);
    int ph  = (r - 31) - S*q_r;

    int tid = threadIdx.x;
    int tx = tid & 15, ty = tid >> 4;
    int no0 = ty * 8;
    int tbase = 4*tx;

    // stage Zs with fused pooling; accumulate l1 over owned window (r==0 blocks)
    float lacc = 0.f;
    for (int i = tid; i < NAC*ZW; i += 256) {
        int ni = i / ZW, jw = i - ni*ZW;
        int j = w0 + q_r + jw;
        float v = 0.f;
        if (j >= 0 && j < LS) {
            size_t base = ((size_t)b*NAC + ni)*LL + (size_t)j*S;
            float sum = 0.f;
            #pragma unroll
            for (int q = 0; q < S; q++) {
                float t = g_zraw[base+q];
                if (IDX >= 1) t -= g_R4[base+q];
                if (IDX == 2) t -= g_R2[base+q];
                sum += t;
            }
            v = sum * (1.f/(float)S);
            if (r == 0 && jw >= -q_r && jw < -q_r + 64) lacc += fabsf(v);
        }
        Zs[ni*ZR + jw] = v;
    }
    // l1 block reduction (also orders Zs before compute)
    red[tid] = lacc;
    __syncthreads();
    for (int o = 128; o > 0; o >>= 1) {
        if (tid < o) red[tid] += red[tid+o];
        __syncthreads();
    }
    if (tid == 0 && r == 0) g_part[IDX*512 + b*8 + wt] = red[0];

    // prefetch ni = 0 W slice
    float4 pf[NPF];
    {
        const float4* src = (const float4*)(W + ((size_t)(0*S + ph)*TP)*NAC);
        #pragma unroll
        for (int u = 0; u < NPF; u++) {
            int i = tid + u*256;
            if (i < N4) pf[u] = src[i];
        }
    }

    ull acc2[4][4];
    #pragma unroll
    for (int p = 0; p < 4; p++)
        #pragma unroll
        for (int j = 0; j < 4; j++) acc2[p][j] = pack2(0.f, 0.f);

    for (int ni = 0; ni < NAC; ni++) {
        float* Acur = As + (ni & 1)*ABUF;
        {   // STS into buffer not read by the (possibly still running) previous compute
            float4* dst = (float4*)Acur;
            #pragma unroll
            for (int u = 0; u < NPF; u++) {
                int i = tid + u*256;
                if (i < N4) dst[i] = pf[u];
            }
        }
        __syncthreads();   // single barrier per ni: STS visible + prev compute done
        if (ni + 1 < NAC) {
            const float4* src = (const float4*)(W + ((size_t)((ni+1)*S + ph)*TP)*NAC);
            #pragma unroll
            for (int u = 0; u < NPF; u++) {
                int i = tid + u*256;
                if (i < N4) pf[u] = src[i];
            }
        }
        const float* zrow = Zs + ni*ZR + tbase;
        ull q0 = pack2(zrow[0], zrow[0]);
        ull q1 = pack2(zrow[1], zrow[1]);
        ull q2 = pack2(zrow[2], zrow[2]);
        #pragma unroll 4
        for (int jj = 0; jj < TP; jj++) {
            float z3 = zrow[jj+3];
            ull q3 = pack2(z3, z3);
            const ull* arow = (const ull*)(Acur + jj*NAC + no0);
            #pragma unroll
            for (int p = 0; p < 4; p++) {
                ull a2 = arow[p];
                ffma2(acc2[p][0], a2, q0);
                ffma2(acc2[p][1], a2, q1);
                ffma2(acc2[p][2], a2, q2);
                ffma2(acc2[p][3], a2, q3);
            }
            q0 = q1; q1 = q2; q2 = q3;
        }
    }

    float* Rb = Rout + (size_t)b*NAC*LL;
    #pragma unroll
    for (int p = 0; p < 4; p++) {
        #pragma unroll
        for (int j = 0; j < 4; j++) {
            float2 v = unpack2(acc2[p][j]);
            int no = no0 + 2*p;
            int t  = S*(w0 + tbase + j) + r;
            Rb[(size_t)no*LL + t]     = v.x;
            Rb[(size_t)(no+1)*LL + t] = v.y;
        }
    }
}

// ---------------- decoder: sum R4+R2+R1, folded weights + denorm ----------------
__global__ void k_dec(const float* __restrict__ dec_b, float* __restrict__ out) {
    __shared__ float Rs[NAC][19];
    int b  = blockIdx.y;
    int p0 = blockIdx.x * 16;
    int tid = threadIdx.x;
    int r = tid & 31, c = tid >> 5;

    size_t boff = (size_t)b*NAC*LL;
    for (int i = tid; i < NAC*18; i += 384) {
        int na = i / 18, pp = i - na*18;
        int p = p0 - 1 + pp;
        float v = 0.f;
        if (p >= 0 && p < LL) {
            size_t idx = boff + (size_t)na*LL + p;
            v = g_R4[idx] + g_R2[idx] + g_R1[idx];
        }
        Rs[na][pp] = v;
    }
    __syncthreads();

    float acc[16];
    #pragma unroll
    for (int i = 0; i < 16; i++) acc[i] = 0.f;

    for (int na = 0; na < NAC; na++) {
        const float* wf = g_Wf + ((size_t)na*3)*CINC*32 + c*32 + r;
        float w0 = wf[0];
        float w1 = wf[CINC*32];
        float w2 = wf[2*CINC*32];
        #pragma unroll
        for (int pl = 0; pl < 16; pl++)
            acc[pl] += w0*Rs[na][pl] + w1*Rs[na][pl+1] + w2*Rs[na][pl+2];
    }

    float sd  = g_std [b*CINC + c];
    float mnv = g_mean[b*CINC + c];
    float db  = dec_b[c];
    #pragma unroll
    for (int pl = 0; pl < 16; pl++) {
        int p = p0 + pl;
        if (p < 511) {
            int t = p*32 + r;
            out[((size_t)b*CINC + c)*TT + t] = (acc[pl] + db)*sd + mnv;
        }
    }
}

// ---------------- finalize scalars ----------------
__global__ void k_final(float* __restrict__ out, int out_size) {
    if (blockIdx.x != 0 || threadIdx.x != 0) return;
    float tot = 0.f;
    const float cnt[3] = { (float)(NB*NAC*(LL/4)), (float)(NB*NAC*(LL/2)), (float)(NB*NAC*LL) };
    for (int sIdx = 0; sIdx < 3; sIdx++) {
        float ssum = 0.f;
        for (int i = 0; i < 512; i++) ssum += g_part[sIdx*512 + i];
        tot += ssum / cnt[sIdx];
    }
    if (out_size > NOUT)     out[NOUT]     = 0.f;
    if (out_size > NOUT + 1) out[NOUT + 1] = tot * 0.01f;
}

// ---------------- launch ----------------
extern "C" void kernel_launch(void* const* d_in, const int* in_sizes, int n_in,
                              void* d_out, int out_size) {
    const float* x        = (const float*)d_in[0];
    const float* stem_w1  = (const float*)d_in[1];
    const float* stem_b1  = (const float*)d_in[2];
    const float* stem_w2  = (const float*)d_in[3];
    const float* stem_b2  = (const float*)d_in[4];
    const float* stem_sc  = (const float*)d_in[5];
    const float* shapelet = (const float*)d_in[6];
    const float* dec_w    = (const float*)d_in[7];
    const float* dec_b    = (const float*)d_in[8];
    float* out = (float*)d_out;

    const int SM4 = (NAC*(17+65) + 2*17*NAC) * (int)sizeof(float);  //  59392
    const int SM2 = (NAC*(33+65) + 2*33*NAC) * (int)sizeof(float);  //  83968
    const int SM1 = (NAC*(64+65) + 2*64*NAC) * (int)sizeof(float);  // 131584
    const int SMEM_STEM = (CINC*594*2 + 64*68 + 4*64*SL + 64*SL) * (int)sizeof(float); // 94912
    cudaFuncSetAttribute(k_fconv<4,17,0>, cudaFuncAttributeMaxDynamicSharedMemorySize, SM4);
    cudaFuncSetAttribute(k_fconv<2,33,1>, cudaFuncAttributeMaxDynamicSharedMemorySize, SM2);
    cudaFuncSetAttribute(k_fconv<1,64,2>, cudaFuncAttributeMaxDynamicSharedMemorySize, SM1);
    cudaFuncSetAttribute(k_stem, cudaFuncAttributeMaxDynamicSharedMemorySize, SMEM_STEM);

    k_prep_all<<<1088, 256>>>(x, shapelet, stem_w1, dec_w);
    k_stem<<<dim3(LL/SL, NB), 256, SMEM_STEM>>>(x, stem_b1, stem_w2, stem_b2, stem_sc);

    k_fconv<4,17,0><<<dim3(8, NB), 256, SM4>>>();   // scale 4: pool(zraw) -> R4
    k_fconv<2,33,1><<<dim3(8, NB), 256, SM2>>>();   // scale 2: pool(zraw-R4) -> R2
    k_fconv<1,64,2><<<dim3(8, NB), 256, SM1>>>();   // scale 1: zraw-R4-R2 -> R1

    k_dec<<<dim3(32, NB), 384>>>(dec_b, out);
    k_final<<<1, 32>>>(out, out_size);
}